// round 3
// baseline (speedup 1.0000x reference)
#include <cuda_runtime.h>
#include <math.h>

#define D_MODEL 512
#define N_HEADS 8
#define HEAD_DIM 64
#define BATCH 4
#define SEQQ 2048
#define SEQK 2048

// Scratch: head-split Q/K/V [B,H,S,hd] and gelu(ctx) [B,S,D]
__device__ float g_Q[BATCH * N_HEADS * SEQQ * HEAD_DIM];
__device__ float g_K[BATCH * N_HEADS * SEQK * HEAD_DIM];
__device__ float g_V[BATCH * N_HEADS * SEQK * HEAD_DIM];
__device__ float g_ctx[BATCH * SEQQ * D_MODEL];

// ---------------------------------------------------------------------------
// NT GEMM: C[m,n] = sum_k A[m,k] * W[n,k] + bias[n]
// A: [M,K] row-major, W: [N,K] row-major.
// MODE 0: C stored [M,N] row-major.
// MODE 1: head-split store: m=(b,s), n=(h,d) -> C[((b*H+h)*S+s)*hd+d]
// BM=BN=64, BK=16, 128 threads, 8x4 per-thread tile, double-buffered smem.
// ---------------------------------------------------------------------------
template <int MODE>
__global__ __launch_bounds__(128) void gemm_nt_kernel(
    const float* __restrict__ A, const float* __restrict__ W,
    const float* __restrict__ bias, float* __restrict__ C,
    int M, int N, int K, int S) {
  __shared__ float As[2][16][68];
  __shared__ float Bs[2][16][68];

  const int tid = threadIdx.x;
  const int m0 = blockIdx.x * 64;
  const int n0 = blockIdx.y * 64;
  const int tm = tid >> 4;   // 0..7  -> rows tm*8 .. +7
  const int tn = tid & 15;   // 0..15 -> cols tn + 16*j

  const int lrow = tid >> 1;       // 0..63
  const int lk = (tid & 1) * 8;    // 0 or 8

  float acc[8][4];
#pragma unroll
  for (int i = 0; i < 8; i++)
#pragma unroll
    for (int j = 0; j < 4; j++) acc[i][j] = 0.f;

  const float* Ap = A + (long)(m0 + lrow) * K + lk;
  const float* Wp = W + (long)(n0 + lrow) * K + lk;

  // prologue: fill buffer 0 with k0 = 0
  {
    float4 a0 = __ldg((const float4*)(Ap));
    float4 a1 = __ldg((const float4*)(Ap + 4));
    float4 b0 = __ldg((const float4*)(Wp));
    float4 b1 = __ldg((const float4*)(Wp + 4));
    As[0][lk + 0][lrow] = a0.x; As[0][lk + 1][lrow] = a0.y;
    As[0][lk + 2][lrow] = a0.z; As[0][lk + 3][lrow] = a0.w;
    As[0][lk + 4][lrow] = a1.x; As[0][lk + 5][lrow] = a1.y;
    As[0][lk + 6][lrow] = a1.z; As[0][lk + 7][lrow] = a1.w;
    Bs[0][lk + 0][lrow] = b0.x; Bs[0][lk + 1][lrow] = b0.y;
    Bs[0][lk + 2][lrow] = b0.z; Bs[0][lk + 3][lrow] = b0.w;
    Bs[0][lk + 4][lrow] = b1.x; Bs[0][lk + 5][lrow] = b1.y;
    Bs[0][lk + 6][lrow] = b1.z; Bs[0][lk + 7][lrow] = b1.w;
  }
  __syncthreads();

  const int nIter = K / 16;
  int buf = 0;
  for (int it = 0; it < nIter; it++) {
    float4 na0, na1, nb0, nb1;
    const bool has_next = (it + 1) < nIter;
    if (has_next) {
      int k0n = (it + 1) * 16;
      na0 = __ldg((const float4*)(Ap + k0n));
      na1 = __ldg((const float4*)(Ap + k0n + 4));
      nb0 = __ldg((const float4*)(Wp + k0n));
      nb1 = __ldg((const float4*)(Wp + k0n + 4));
    }
#pragma unroll
    for (int k = 0; k < 16; k++) {
      float af[8], bf[4];
#pragma unroll
      for (int i = 0; i < 8; i++) af[i] = As[buf][k][tm * 8 + i];
#pragma unroll
      for (int j = 0; j < 4; j++) bf[j] = Bs[buf][k][tn + 16 * j];
#pragma unroll
      for (int i = 0; i < 8; i++)
#pragma unroll
        for (int j = 0; j < 4; j++) acc[i][j] = fmaf(af[i], bf[j], acc[i][j]);
    }
    if (has_next) {
      int nb = buf ^ 1;
      As[nb][lk + 0][lrow] = na0.x; As[nb][lk + 1][lrow] = na0.y;
      As[nb][lk + 2][lrow] = na0.z; As[nb][lk + 3][lrow] = na0.w;
      As[nb][lk + 4][lrow] = na1.x; As[nb][lk + 5][lrow] = na1.y;
      As[nb][lk + 6][lrow] = na1.z; As[nb][lk + 7][lrow] = na1.w;
      Bs[nb][lk + 0][lrow] = nb0.x; Bs[nb][lk + 1][lrow] = nb0.y;
      Bs[nb][lk + 2][lrow] = nb0.z; Bs[nb][lk + 3][lrow] = nb0.w;
      Bs[nb][lk + 4][lrow] = nb1.x; Bs[nb][lk + 5][lrow] = nb1.y;
      Bs[nb][lk + 6][lrow] = nb1.z; Bs[nb][lk + 7][lrow] = nb1.w;
      __syncthreads();
      buf = nb;
    }
  }

#pragma unroll
  for (int i = 0; i < 8; i++) {
    int m = m0 + tm * 8 + i;
#pragma unroll
    for (int j = 0; j < 4; j++) {
      int n = n0 + tn + 16 * j;
      float v = acc[i][j] + __ldg(bias + n);
      if (MODE == 0) {
        C[(long)m * N + n] = v;
      } else {
        int b = m / S, s = m - b * S;
        int h = n >> 6, d = n & 63;
        C[(((long)(b * N_HEADS + h)) * S + s) * HEAD_DIM + d] = v;
      }
    }
  }
}

// ---------------------------------------------------------------------------
// Flash attention per (b, h, 64-row q tile). BK tile = 32 keys.
// Scale 1/sqrt(64) folded into Q load. GELU fused on output.
// Softmax state (m, l) kept in smem so all 128 threads participate.
// ---------------------------------------------------------------------------
__global__ __launch_bounds__(128) void flash_kernel(
    const float* __restrict__ Q, const float* __restrict__ K,
    const float* __restrict__ V, float* __restrict__ ctx) {
  __shared__ float Qt[64][64];   // [d][q]   16 KB
  __shared__ float Kt[64][32];   // [d][key]  8 KB
  __shared__ float Vs[32][64];   // [key][d]  8 KB
  __shared__ float Ps[32][66];   // [key][q]  8.25 KB (padded)
  __shared__ float alphas[64];
  __shared__ float m_s[64], l_s[64];
  __shared__ float pmax[2][64], psum[2][64];

  const int tid = threadIdx.x;
  const int q0 = blockIdx.x * 64;
  const int h = blockIdx.y;
  const int b = blockIdx.z;

  const float* Qb = Q + ((long)(b * N_HEADS + h) * SEQQ + q0) * HEAD_DIM;
  const float* Kb = K + (long)(b * N_HEADS + h) * SEQK * HEAD_DIM;
  const float* Vb = V + (long)(b * N_HEADS + h) * SEQK * HEAD_DIM;

  const float scale = 0.125f;  // 1/sqrt(64)
#pragma unroll
  for (int it = 0; it < 8; it++) {
    int id = tid + it * 128;        // 0..1023 : 64 rows x 16 float4
    int row = id >> 4;
    int d4 = (id & 15) * 4;
    float4 v = *(const float4*)(Qb + row * HEAD_DIM + d4);
    Qt[d4 + 0][row] = v.x * scale;
    Qt[d4 + 1][row] = v.y * scale;
    Qt[d4 + 2][row] = v.z * scale;
    Qt[d4 + 3][row] = v.w * scale;
  }
  if (tid < 64) {
    m_s[tid] = -INFINITY;
    l_s[tid] = 0.f;
  }

  const int tm = tid >> 3;  // 0..15 -> S/O rows tm*4 .. +3
  const int tn = tid & 7;   // 0..7  -> S cols tn*4..+3 ; O cols tn+8*j
  const int srow = tid & 63;   // softmax: q row
  const int shalf = tid >> 6;  // softmax: 0/1 -> cols shalf*16..+15

  float O[4][8];
#pragma unroll
  for (int i = 0; i < 4; i++)
#pragma unroll
    for (int j = 0; j < 8; j++) O[i][j] = 0.f;

  for (int t = 0; t < SEQK / 32; t++) {
    __syncthreads();  // prev iter done reading Kt/Vs/Ps; Qt/m_s init visible
#pragma unroll
    for (int it = 0; it < 4; it++) {
      int id = tid + it * 128;      // 0..511 : 32 rows x 16 float4
      int c = id >> 4;
      int d4 = (id & 15) * 4;
      float4 kv = *(const float4*)(Kb + (long)(t * 32 + c) * HEAD_DIM + d4);
      Kt[d4 + 0][c] = kv.x; Kt[d4 + 1][c] = kv.y;
      Kt[d4 + 2][c] = kv.z; Kt[d4 + 3][c] = kv.w;
      float4 vv = *(const float4*)(Vb + (long)(t * 32 + c) * HEAD_DIM + d4);
      *(float4*)(&Vs[c][d4]) = vv;
    }
    __syncthreads();

    // S = (Q*scale) @ K^T  -> 64x32, per-thread 4x4
    float acc[4][4];
#pragma unroll
    for (int i = 0; i < 4; i++)
#pragma unroll
      for (int j = 0; j < 4; j++) acc[i][j] = 0.f;
#pragma unroll 16
    for (int k = 0; k < 64; k++) {
      float qf[4], kf[4];
#pragma unroll
      for (int i = 0; i < 4; i++) qf[i] = Qt[k][tm * 4 + i];
#pragma unroll
      for (int j = 0; j < 4; j++) kf[j] = Kt[k][tn * 4 + j];
#pragma unroll
      for (int i = 0; i < 4; i++)
#pragma unroll
        for (int j = 0; j < 4; j++) acc[i][j] = fmaf(qf[i], kf[j], acc[i][j]);
    }
#pragma unroll
    for (int i = 0; i < 4; i++)
#pragma unroll
      for (int j = 0; j < 4; j++) Ps[tn * 4 + j][tm * 4 + i] = acc[i][j];
    __syncthreads();

    // online softmax: 2 threads per q row, 16 cols each
    {
      float pm = -INFINITY;
#pragma unroll
      for (int c = 0; c < 16; c++)
        pm = fmaxf(pm, Ps[shalf * 16 + c][srow]);
      pmax[shalf][srow] = pm;
      __syncthreads();
      float m_old = m_s[srow];
      float m_new = fmaxf(m_old, fmaxf(pmax[0][srow], pmax[1][srow]));
      float ssum = 0.f;
#pragma unroll
      for (int c = 0; c < 16; c++) {
        float p = __expf(Ps[shalf * 16 + c][srow] - m_new);
        Ps[shalf * 16 + c][srow] = p;
        ssum += p;
      }
      psum[shalf][srow] = ssum;
      __syncthreads();
      if (shalf == 0) {
        float alpha = __expf(m_old - m_new);
        l_s[srow] = l_s[srow] * alpha + psum[0][srow] + psum[1][srow];
        m_s[srow] = m_new;
        alphas[srow] = alpha;
      }
    }
    __syncthreads();

    // O = O*alpha + P @ V
#pragma unroll
    for (int i = 0; i < 4; i++) {
      float a = alphas[tm * 4 + i];
#pragma unroll
      for (int j = 0; j < 8; j++) O[i][j] *= a;
    }
#pragma unroll 8
    for (int c = 0; c < 32; c++) {
      float pr[4], vf[8];
#pragma unroll
      for (int i = 0; i < 4; i++) pr[i] = Ps[c][tm * 4 + i];
#pragma unroll
      for (int j = 0; j < 8; j++) vf[j] = Vs[c][tn + 8 * j];
#pragma unroll
      for (int i = 0; i < 4; i++)
#pragma unroll
        for (int j = 0; j < 8; j++) O[i][j] = fmaf(pr[i], vf[j], O[i][j]);
    }
  }
  __syncthreads();

  float* outb = ctx + ((long)(b * SEQQ + q0)) * D_MODEL + h * HEAD_DIM;
#pragma unroll
  for (int i = 0; i < 4; i++) {
    float li = 1.f / l_s[tm * 4 + i];
    float* orow = outb + (long)(tm * 4 + i) * D_MODEL + tn;
#pragma unroll
    for (int j = 0; j < 8; j++) {
      float x = O[i][j] * li;
      // exact (erf) GELU
      float g = 0.5f * x * (1.f + erff(x * 0.70710678118654752f));
      orow[8 * j] = g;
    }
  }
}

extern "C" void kernel_launch(void* const* d_in, const int* in_sizes, int n_in,
                              void* d_out, int out_size) {
  const float* query = (const float*)d_in[0];
  const float* key = (const float*)d_in[1];
  const float* value = (const float*)d_in[2];
  const float* Wq = (const float*)d_in[3];
  const float* bq = (const float*)d_in[4];
  const float* Wk = (const float*)d_in[5];
  const float* bk = (const float*)d_in[6];
  const float* Wv = (const float*)d_in[7];
  const float* bv = (const float*)d_in[8];
  const float* Wo = (const float*)d_in[9];
  const float* bo = (const float*)d_in[10];

  float *Qp, *Kp, *Vp, *Cp;
  cudaGetSymbolAddress((void**)&Qp, g_Q);
  cudaGetSymbolAddress((void**)&Kp, g_K);
  cudaGetSymbolAddress((void**)&Vp, g_V);
  cudaGetSymbolAddress((void**)&Cp, g_ctx);

  const int M = BATCH * SEQQ;  // 8192
  dim3 ggrid(M / 64, D_MODEL / 64);

  // QKV projections (head-split output layout)
  gemm_nt_kernel<1><<<ggrid, 128>>>(query, Wq, bq, Qp, M, D_MODEL, D_MODEL, SEQQ);
  gemm_nt_kernel<1><<<ggrid, 128>>>(key, Wk, bk, Kp, M, D_MODEL, D_MODEL, SEQK);
  gemm_nt_kernel<1><<<ggrid, 128>>>(value, Wv, bv, Vp, M, D_MODEL, D_MODEL, SEQK);

  // Flash attention + fused GELU -> g_ctx [B,SQ,D]
  dim3 fgrid(SEQQ / 64, N_HEADS, BATCH);
  flash_kernel<<<fgrid, 128>>>(Qp, Kp, Vp, Cp);

  // Output projection
  gemm_nt_kernel<0><<<ggrid, 128>>>(Cp, Wo, bo, (float*)d_out, M, D_MODEL,
                                    D_MODEL, SEQQ);
}

// round 17
// speedup vs baseline: 2.5241x; 2.5241x over previous
#include <cuda_runtime.h>
#include <cuda_bf16.h>
#include <math.h>
#include <stdint.h>

#define D_MODEL 512
#define N_HEADS 8
#define HEAD_DIM 64
#define BATCH 4
#define SEQQ 2048
#define SEQK 2048

// Scratch: head-split Q/K/V [B,H,S,hd] and gelu(ctx) [B,S,D]
__device__ float g_Q[BATCH * N_HEADS * SEQQ * HEAD_DIM];
__device__ float g_K[BATCH * N_HEADS * SEQK * HEAD_DIM];
__device__ float g_V[BATCH * N_HEADS * SEQK * HEAD_DIM];
__device__ float g_ctx[BATCH * SEQQ * D_MODEL];

// ===========================================================================
// helpers: ldmatrix + mma.sync (bf16), portable PTX (no tcgen05)
// ===========================================================================
__device__ __forceinline__ uint32_t smem_u32(const void* p) {
  uint32_t a;
  asm("{ .reg .u64 t; cvta.to.shared.u64 t, %1; cvt.u32.u64 %0, t; }"
      : "=r"(a) : "l"(p));
  return a;
}
__device__ __forceinline__ void ldm_x4(uint32_t& r0, uint32_t& r1, uint32_t& r2,
                                       uint32_t& r3, uint32_t a) {
  asm volatile("ldmatrix.sync.aligned.m8n8.x4.shared.b16 {%0,%1,%2,%3}, [%4];"
               : "=r"(r0), "=r"(r1), "=r"(r2), "=r"(r3) : "r"(a));
}
__device__ __forceinline__ void ldm_x2(uint32_t& r0, uint32_t& r1, uint32_t a) {
  asm volatile("ldmatrix.sync.aligned.m8n8.x2.shared.b16 {%0,%1}, [%2];"
               : "=r"(r0), "=r"(r1) : "r"(a));
}
__device__ __forceinline__ void ldm_x2t(uint32_t& r0, uint32_t& r1, uint32_t a) {
  asm volatile("ldmatrix.sync.aligned.m8n8.x2.trans.shared.b16 {%0,%1}, [%2];"
               : "=r"(r0), "=r"(r1) : "r"(a));
}
__device__ __forceinline__ void mma_bf(float c[4], const uint32_t a[4],
                                       uint32_t b0, uint32_t b1) {
  asm volatile(
      "mma.sync.aligned.m16n8k16.row.col.f32.bf16.bf16.f32 "
      "{%0,%1,%2,%3}, {%4,%5,%6,%7}, {%8,%9}, {%0,%1,%2,%3};"
      : "+f"(c[0]), "+f"(c[1]), "+f"(c[2]), "+f"(c[3])
      : "r"(a[0]), "r"(a[1]), "r"(a[2]), "r"(a[3]), "r"(b0), "r"(b1));
}
__device__ __forceinline__ uint32_t pkbf(float x, float y) {
  return (uint32_t)__bfloat16_as_ushort(__float2bfloat16(x)) |
         ((uint32_t)__bfloat16_as_ushort(__float2bfloat16(y)) << 16);
}
// split fp32 pair into bf16 hi pair + bf16 residual pair
__device__ __forceinline__ void split2(float x, float y, uint32_t& hi, uint32_t& lo) {
  __nv_bfloat16 hx = __float2bfloat16(x), hy = __float2bfloat16(y);
  hi = (uint32_t)__bfloat16_as_ushort(hx) | ((uint32_t)__bfloat16_as_ushort(hy) << 16);
  lo = pkbf(x - __bfloat162float(hx), y - __bfloat162float(hy));
}

// Row stride for all bf16 smem tiles: 72 elements = 144 bytes (conflict-free
// ldmatrix: bank = (36*row + x) % 32 = (4*row + x) % 32 distinct over 8 rows).
#define RSB 144

// A fragment (m16k16) from row-major [m][k] tile
__device__ __forceinline__ void ldm_afrag(uint32_t r[4], uint32_t base, int m0, int k0) {
  int lane = threadIdx.x & 31;
  int seg = lane >> 3;
  uint32_t a = base + (uint32_t)((m0 + (seg & 1) * 8 + (lane & 7)) * RSB +
                                 (k0 + (seg >> 1) * 8) * 2);
  ldm_x4(r[0], r[1], r[2], r[3], a);
}
// B fragment (k16n8) from row-major [n][k] tile (NT operand)
__device__ __forceinline__ void ldm_bfrag(uint32_t& b0, uint32_t& b1, uint32_t base,
                                          int n0, int k0) {
  int lane = threadIdx.x & 31;
  uint32_t a = base + (uint32_t)((n0 + (lane & 7)) * RSB +
                                 (k0 + ((lane >> 3) & 1) * 8) * 2);
  ldm_x2(b0, b1, a);
}
// B fragment (k16n8) from row-major [k][n] tile via transposing ldmatrix
__device__ __forceinline__ void ldm_bfragT(uint32_t& b0, uint32_t& b1, uint32_t base,
                                           int k0, int n0) {
  int lane = threadIdx.x & 31;
  uint32_t a = base + (uint32_t)((k0 + (lane & 15)) * RSB + n0 * 2);
  ldm_x2t(b0, b1, a);
}

// ===========================================================================
// NT GEMM on mma.sync, bf16 hi/lo split (3 MMAs): C = A·W^T + bias
// Tile 128x128, 256 threads (warp grid 4x2, warp tile 32x64), BK=64, K=512.
// MODE 0: [M,N] row-major. MODE 1: head-split.
// ===========================================================================
#define GM_AH 0
#define GM_AL 18432
#define GM_BH 36864
#define GM_BL 55296
#define GM_SMEM 73728

template <int MODE>
__global__ __launch_bounds__(256) void gemm_mma_kernel(
    const float* __restrict__ A, const float* __restrict__ W,
    const float* __restrict__ bias, float* __restrict__ C) {
  extern __shared__ char sm[];
  const uint32_t sb = smem_u32(sm);
  const int tid = threadIdx.x;
  const int wid = tid >> 5, lane = tid & 31;
  const int wm = wid & 3, wn = wid >> 2;  // 4 x 2 warp grid
  const int g = lane >> 2, qd = lane & 3;
  const int m0b = blockIdx.x * 128, n0b = blockIdx.y * 128;

  float c[2][8][4];
#pragma unroll
  for (int mt = 0; mt < 2; mt++)
#pragma unroll
    for (int nt = 0; nt < 8; nt++)
#pragma unroll
      for (int i = 0; i < 4; i++) c[mt][nt][i] = 0.f;

  for (int t = 0; t < 8; t++) {
    __syncthreads();  // prev iter frag reads done
    const int k0 = t * 64;
#pragma unroll
    for (int it = 0; it < 8; it++) {
      int id = tid + it * 256;  // 0..2047 : 128 rows x 16 float4
      int row = id >> 4;
      int kq = (id & 15) * 4;
      float4 v = __ldg((const float4*)(A + (long)(m0b + row) * D_MODEL + k0 + kq));
      uint32_t h0, l0, h1, l1;
      split2(v.x, v.y, h0, l0);
      split2(v.z, v.w, h1, l1);
      *(uint2*)(sm + GM_AH + row * RSB + kq * 2) = make_uint2(h0, h1);
      *(uint2*)(sm + GM_AL + row * RSB + kq * 2) = make_uint2(l0, l1);
      float4 w = __ldg((const float4*)(W + (long)(n0b + row) * D_MODEL + k0 + kq));
      split2(w.x, w.y, h0, l0);
      split2(w.z, w.w, h1, l1);
      *(uint2*)(sm + GM_BH + row * RSB + kq * 2) = make_uint2(h0, h1);
      *(uint2*)(sm + GM_BL + row * RSB + kq * 2) = make_uint2(l0, l1);
    }
    __syncthreads();

#pragma unroll
    for (int kk = 0; kk < 4; kk++) {
      uint32_t aH[2][4], aL[2][4];
#pragma unroll
      for (int mt = 0; mt < 2; mt++) {
        ldm_afrag(aH[mt], sb + GM_AH, wm * 32 + mt * 16, kk * 16);
        ldm_afrag(aL[mt], sb + GM_AL, wm * 32 + mt * 16, kk * 16);
      }
#pragma unroll
      for (int nt = 0; nt < 8; nt++) {
        uint32_t bh0, bh1, bl0, bl1;
        ldm_bfrag(bh0, bh1, sb + GM_BH, wn * 64 + nt * 8, kk * 16);
        ldm_bfrag(bl0, bl1, sb + GM_BL, wn * 64 + nt * 8, kk * 16);
#pragma unroll
        for (int mt = 0; mt < 2; mt++) {
          mma_bf(c[mt][nt], aH[mt], bh0, bh1);
          mma_bf(c[mt][nt], aH[mt], bl0, bl1);
          mma_bf(c[mt][nt], aL[mt], bh0, bh1);
        }
      }
    }
  }

  // epilogue
#pragma unroll
  for (int mt = 0; mt < 2; mt++) {
#pragma unroll
    for (int nt = 0; nt < 8; nt++) {
      int row0 = m0b + wm * 32 + mt * 16 + g;
      int col = n0b + wn * 64 + nt * 8 + qd * 2;
      float2 bv = *(const float2*)(bias + col);
      float2 v0 = make_float2(c[mt][nt][0] + bv.x, c[mt][nt][1] + bv.y);
      float2 v1 = make_float2(c[mt][nt][2] + bv.x, c[mt][nt][3] + bv.y);
      if (MODE == 0) {
        *(float2*)(C + (long)row0 * D_MODEL + col) = v0;
        *(float2*)(C + (long)(row0 + 8) * D_MODEL + col) = v1;
      } else {
        int h = col >> 6, d = col & 63;
        int b0r = row0 >> 11, s0 = row0 & 2047;
        *(float2*)(C + (((long)(b0r * N_HEADS + h)) * SEQQ + s0) * HEAD_DIM + d) = v0;
        int row1 = row0 + 8;
        int b1r = row1 >> 11, s1 = row1 & 2047;
        *(float2*)(C + (((long)(b1r * N_HEADS + h)) * SEQQ + s1) * HEAD_DIM + d) = v1;
      }
    }
  }
}

// ===========================================================================
// Flash attention on mma.sync, bf16 hi/lo split.
// BQ=128 q rows per CTA, 256 threads (8 warps x 16 rows), key tiles of 64.
// Softmax fully in registers (quad shfl); P->A frags in-register; V consumed
// via ldmatrix.trans (no smem transpose). GELU fused on output.
// ===========================================================================
#define FL_QH 0
#define FL_QL 18432
#define FL_KH 36864
#define FL_KL 46080
#define FL_VH 55296
#define FL_VL 64512
#define FL_SMEM 73728

__global__ __launch_bounds__(256) void flash_kernel(
    const float* __restrict__ Q, const float* __restrict__ K,
    const float* __restrict__ V, float* __restrict__ ctx) {
  extern __shared__ char sm[];
  const uint32_t sb = smem_u32(sm);
  const int tid = threadIdx.x;
  const int wid = tid >> 5, lane = tid & 31;
  const int g = lane >> 2, qd = lane & 3;
  const int q0 = blockIdx.x * 128;
  const int h = blockIdx.y, b = blockIdx.z;
  const int mrow = wid * 16;

  const float* Qb = Q + ((long)(b * N_HEADS + h) * SEQQ + q0) * HEAD_DIM;
  const float* Kb = K + (long)(b * N_HEADS + h) * SEQK * HEAD_DIM;
  const float* Vb = V + (long)(b * N_HEADS + h) * SEQK * HEAD_DIM;

  // load Q tile (scaled by 1/8), split to QH/QL
#pragma unroll
  for (int it = 0; it < 8; it++) {
    int id = tid + it * 256;  // 0..2047 : 128 rows x 16 float4
    int row = id >> 4;
    int kq = (id & 15) * 4;
    float4 v = *(const float4*)(Qb + row * HEAD_DIM + kq);
    v.x *= 0.125f; v.y *= 0.125f; v.z *= 0.125f; v.w *= 0.125f;
    uint32_t h0, l0, h1, l1;
    split2(v.x, v.y, h0, l0);
    split2(v.z, v.w, h1, l1);
    *(uint2*)(sm + FL_QH + row * RSB + kq * 2) = make_uint2(h0, h1);
    *(uint2*)(sm + FL_QL + row * RSB + kq * 2) = make_uint2(l0, l1);
  }

  float o[8][4];
#pragma unroll
  for (int nt = 0; nt < 8; nt++)
#pragma unroll
    for (int i = 0; i < 4; i++) o[nt][i] = 0.f;
  float m0r = -INFINITY, m1r = -INFINITY, l0r = 0.f, l1r = 0.f;

  for (int t = 0; t < SEQK / 64; t++) {
    __syncthreads();  // prev iter frag reads done; Q tile visible (t=0)
#pragma unroll
    for (int it = 0; it < 4; it++) {
      int id = tid + it * 256;  // 0..1023 : 64 rows x 16 float4
      int row = id >> 4;
      int kq = (id & 15) * 4;
      float4 kv = *(const float4*)(Kb + (long)(t * 64 + row) * HEAD_DIM + kq);
      uint32_t h0, l0, h1, l1;
      split2(kv.x, kv.y, h0, l0);
      split2(kv.z, kv.w, h1, l1);
      *(uint2*)(sm + FL_KH + row * RSB + kq * 2) = make_uint2(h0, h1);
      *(uint2*)(sm + FL_KL + row * RSB + kq * 2) = make_uint2(l0, l1);
      float4 vv = *(const float4*)(Vb + (long)(t * 64 + row) * HEAD_DIM + kq);
      split2(vv.x, vv.y, h0, l0);
      split2(vv.z, vv.w, h1, l1);
      *(uint2*)(sm + FL_VH + row * RSB + kq * 2) = make_uint2(h0, h1);
      *(uint2*)(sm + FL_VL + row * RSB + kq * 2) = make_uint2(l0, l1);
    }
    __syncthreads();

    // S = Qs @ K^T : 16 x 64 per warp
    float s[8][4];
#pragma unroll
    for (int nt = 0; nt < 8; nt++)
#pragma unroll
      for (int i = 0; i < 4; i++) s[nt][i] = 0.f;
#pragma unroll
    for (int kk = 0; kk < 4; kk++) {
      uint32_t aH[4], aL[4];
      ldm_afrag(aH, sb + FL_QH, mrow, kk * 16);
      ldm_afrag(aL, sb + FL_QL, mrow, kk * 16);
#pragma unroll
      for (int nt = 0; nt < 8; nt++) {
        uint32_t bh0, bh1, bl0, bl1;
        ldm_bfrag(bh0, bh1, sb + FL_KH, nt * 8, kk * 16);
        ldm_bfrag(bl0, bl1, sb + FL_KL, nt * 8, kk * 16);
        mma_bf(s[nt], aH, bh0, bh1);
        mma_bf(s[nt], aH, bl0, bl1);
        mma_bf(s[nt], aL, bh0, bh1);
      }
    }

    // row max across registers + quad
    float mx0 = -INFINITY, mx1 = -INFINITY;
#pragma unroll
    for (int nt = 0; nt < 8; nt++) {
      mx0 = fmaxf(mx0, fmaxf(s[nt][0], s[nt][1]));
      mx1 = fmaxf(mx1, fmaxf(s[nt][2], s[nt][3]));
    }
    mx0 = fmaxf(mx0, __shfl_xor_sync(0xffffffffu, mx0, 1));
    mx0 = fmaxf(mx0, __shfl_xor_sync(0xffffffffu, mx0, 2));
    mx1 = fmaxf(mx1, __shfl_xor_sync(0xffffffffu, mx1, 1));
    mx1 = fmaxf(mx1, __shfl_xor_sync(0xffffffffu, mx1, 2));
    float mn0 = fmaxf(m0r, mx0), mn1 = fmaxf(m1r, mx1);
    float a0 = __expf(m0r - mn0), a1 = __expf(m1r - mn1);
    m0r = mn0; m1r = mn1;
#pragma unroll
    for (int nt = 0; nt < 8; nt++) {
      o[nt][0] *= a0; o[nt][1] *= a0;
      o[nt][2] *= a1; o[nt][3] *= a1;
    }

    // P = exp(S - m), PV accumulate (P hi/lo in-register -> A frags)
    float sum0 = 0.f, sum1 = 0.f;
#pragma unroll
    for (int kk = 0; kk < 4; kk++) {
      uint32_t pH[4], pL[4];
      {
        int j = 2 * kk;
        float p0 = __expf(s[j][0] - mn0), p1 = __expf(s[j][1] - mn0);
        float p2 = __expf(s[j][2] - mn1), p3 = __expf(s[j][3] - mn1);
        sum0 += p0 + p1; sum1 += p2 + p3;
        split2(p0, p1, pH[0], pL[0]);
        split2(p2, p3, pH[1], pL[1]);
        j = 2 * kk + 1;
        p0 = __expf(s[j][0] - mn0); p1 = __expf(s[j][1] - mn0);
        p2 = __expf(s[j][2] - mn1); p3 = __expf(s[j][3] - mn1);
        sum0 += p0 + p1; sum1 += p2 + p3;
        split2(p0, p1, pH[2], pL[2]);
        split2(p2, p3, pH[3], pL[3]);
      }
#pragma unroll
      for (int nt = 0; nt < 8; nt++) {
        uint32_t bh0, bh1, bl0, bl1;
        ldm_bfragT(bh0, bh1, sb + FL_VH, kk * 16, nt * 8);
        ldm_bfragT(bl0, bl1, sb + FL_VL, kk * 16, nt * 8);
        mma_bf(o[nt], pH, bh0, bh1);
        mma_bf(o[nt], pH, bl0, bl1);
        mma_bf(o[nt], pL, bh0, bh1);
      }
    }
    sum0 += __shfl_xor_sync(0xffffffffu, sum0, 1);
    sum0 += __shfl_xor_sync(0xffffffffu, sum0, 2);
    sum1 += __shfl_xor_sync(0xffffffffu, sum1, 1);
    sum1 += __shfl_xor_sync(0xffffffffu, sum1, 2);
    l0r = l0r * a0 + sum0;
    l1r = l1r * a1 + sum1;
  }

  // epilogue: normalize, exact GELU, store to ctx
  const float inv0 = 1.f / l0r, inv1 = 1.f / l1r;
  float* outb = ctx + ((long)(b * SEQQ + q0)) * D_MODEL + h * HEAD_DIM;
  const int r0 = mrow + g, r1 = mrow + 8 + g;
#pragma unroll
  for (int nt = 0; nt < 8; nt++) {
    int col = nt * 8 + qd * 2;
    float x0 = o[nt][0] * inv0, x1 = o[nt][1] * inv0;
    float x2 = o[nt][2] * inv1, x3 = o[nt][3] * inv1;
    float2 v0, v1;
    v0.x = 0.5f * x0 * (1.f + erff(x0 * 0.70710678118654752f));
    v0.y = 0.5f * x1 * (1.f + erff(x1 * 0.70710678118654752f));
    v1.x = 0.5f * x2 * (1.f + erff(x2 * 0.70710678118654752f));
    v1.y = 0.5f * x3 * (1.f + erff(x3 * 0.70710678118654752f));
    *(float2*)(outb + (long)r0 * D_MODEL + col) = v0;
    *(float2*)(outb + (long)r1 * D_MODEL + col) = v1;
  }
}

extern "C" void kernel_launch(void* const* d_in, const int* in_sizes, int n_in,
                              void* d_out, int out_size) {
  const float* query = (const float*)d_in[0];
  const float* key = (const float*)d_in[1];
  const float* value = (const float*)d_in[2];
  const float* Wq = (const float*)d_in[3];
  const float* bq = (const float*)d_in[4];
  const float* Wk = (const float*)d_in[5];
  const float* bk = (const float*)d_in[6];
  const float* Wv = (const float*)d_in[7];
  const float* bv = (const float*)d_in[8];
  const float* Wo = (const float*)d_in[9];
  const float* bo = (const float*)d_in[10];

  float *Qp, *Kp, *Vp, *Cp;
  cudaGetSymbolAddress((void**)&Qp, g_Q);
  cudaGetSymbolAddress((void**)&Kp, g_K);
  cudaGetSymbolAddress((void**)&Vp, g_V);
  cudaGetSymbolAddress((void**)&Cp, g_ctx);

  cudaFuncSetAttribute(gemm_mma_kernel<0>,
                       cudaFuncAttributeMaxDynamicSharedMemorySize, GM_SMEM);
  cudaFuncSetAttribute(gemm_mma_kernel<1>,
                       cudaFuncAttributeMaxDynamicSharedMemorySize, GM_SMEM);
  cudaFuncSetAttribute(flash_kernel,
                       cudaFuncAttributeMaxDynamicSharedMemorySize, FL_SMEM);

  dim3 ggrid(BATCH * SEQQ / 128, D_MODEL / 128);  // (64, 4)

  gemm_mma_kernel<1><<<ggrid, 256, GM_SMEM>>>(query, Wq, bq, Qp);
  gemm_mma_kernel<1><<<ggrid, 256, GM_SMEM>>>(key, Wk, bk, Kp);
  gemm_mma_kernel<1><<<ggrid, 256, GM_SMEM>>>(value, Wv, bv, Vp);

  dim3 fgrid(SEQQ / 128, N_HEADS, BATCH);  // (16, 8, 4)
  flash_kernel<<<fgrid, 256, FL_SMEM>>>(Qp, Kp, Vp, Cp);

  gemm_mma_kernel<0><<<ggrid, 256, GM_SMEM>>>(Cp, Wo, bo, (float*)d_out);
}